// round 6
// baseline (speedup 1.0000x reference)
#include <cuda_runtime.h>

namespace {
constexpr int NX = 256, NY = 256, NZ = 128;
constexpr int NZ4 = NZ / 4, XS4 = NY * NZ4, FS4 = NX * XS4;

constexpr float CVc = 717.0f;
constexpr float MUc = 1.8e-5f, KTHc = 0.025f, Gc = 9.8f;
constexpr float Rg  = 287.0f;

constexpr double DXd = 1.0 / NX, DYd = 1.0 / NY, DZd = 1.0 / (NZ - 1);
constexpr float inv2dx = (float)(0.5 / DXd);
constexpr float inv2dy = (float)(0.5 / DYd);
constexpr float inv2dz = (float)(0.5 / DZd);
constexpr float invdx2 = (float)(1.0 / (DXd * DXd));
constexpr float invdy2 = (float)(1.0 / (DYd * DYd));
constexpr float invdz2 = (float)(1.0 / (DZd * DZd));
constexpr float kTco   = KTHc / CVc;

__device__ __forceinline__ float4 operator+(float4 a, float4 b){ return make_float4(a.x+b.x, a.y+b.y, a.z+b.z, a.w+b.w); }
__device__ __forceinline__ float4 operator-(float4 a, float4 b){ return make_float4(a.x-b.x, a.y-b.y, a.z-b.z, a.w-b.w); }
__device__ __forceinline__ float4 operator*(float4 a, float4 b){ return make_float4(a.x*b.x, a.y*b.y, a.z*b.z, a.w*b.w); }
__device__ __forceinline__ float4 operator*(float4 a, float s){ return make_float4(a.x*s, a.y*s, a.z*s, a.w*s); }
__device__ __forceinline__ float4 operator*(float s, float4 a){ return a * s; }

__device__ __forceinline__ float4 zm_of(float4 a){
    float p = __shfl_up_sync(0xffffffffu, a.w, 1);
    return make_float4(p, a.x, a.y, a.z);
}
__device__ __forceinline__ float4 zp_of(float4 a){
    float n = __shfl_down_sync(0xffffffffu, a.x, 1);
    return make_float4(a.y, a.z, a.w, n);
}

__device__ __forceinline__ float4 maskwall(float4 v, bool lo, bool hi){
    if (lo) v.x = 0.0f;
    if (hi) v.w = 0.0f;
    return v;
}

__global__ __launch_bounds__(256, 4)
void rb4_kernel(const float4* __restrict__ s, float4* __restrict__ o)
{
    const int lane = threadIdx.x;                       // z chunk (4 z per lane)
    const int y = (blockIdx.x << 3) | threadIdx.y;      // 8 y per block
    const int x = blockIdx.y;

    const int rowc = y * NZ4 + lane;
    const int ic  = x * XS4 + rowc;
    const int ixm = ((x + NX - 1) & (NX - 1)) * XS4 + rowc;
    const int ixp = ((x + 1)      & (NX - 1)) * XS4 + rowc;
    const int iym = x * XS4 + ((y + NY - 1) & (NY - 1)) * NZ4 + lane;
    const int iyp = x * XS4 + ((y + 1)      & (NY - 1)) * NZ4 + lane;

    const bool lo = (lane == 0);
    const bool hi = (lane == 31);

    // persistent live set: uc, vc, wc, rinv, dpd{x,y,z}
    const float4 uc = s[0 * FS4 + ic];
    const float4 vc = s[1 * FS4 + ic];
    const float4 wc = s[2 * FS4 + ic];
    float4 rinv, dpdx, dpdy, dpdz;

    // ---- phase 1: rho & T → dT, pressure gradients, drou ----
    {
        const float4 rc  = s[3 * FS4 + ic];
        const float4 rxm = s[3 * FS4 + ixm], rxp = s[3 * FS4 + ixp];
        const float4 rym = s[3 * FS4 + iym], ryp = s[3 * FS4 + iyp];
        const float4 Tc  = s[4 * FS4 + ic];
        const float4 Txm = s[4 * FS4 + ixm], Txp = s[4 * FS4 + ixp];
        const float4 Tym = s[4 * FS4 + iym], Typ = s[4 * FS4 + iyp];
        const float4 rzm = zm_of(rc), rzp = zp_of(rc);
        const float4 Tzm = zm_of(Tc), Tzp = zp_of(Tc);

        rinv = make_float4(1.0f / rc.x, 1.0f / rc.y, 1.0f / rc.z, 1.0f / rc.w);
        dpdx = (rxp * Txp - rxm * Txm) * (Rg * inv2dx);
        dpdy = (ryp * Typ - rym * Tym) * (Rg * inv2dy);
        dpdz = (rzp * Tzp - rzm * Tzm) * (Rg * inv2dz);

        const float4 lapT = (Txp + Txm - Tc * 2.0f) * invdx2 + (Typ + Tym - Tc * 2.0f) * invdy2 + (Tzp + Tzm - Tc * 2.0f) * invdz2;
        const float4 advT = uc * ((Txp - Txm) * inv2dx) + vc * ((Typ - Tym) * inv2dy) + wc * ((Tzp - Tzm) * inv2dz);
        __stcs(&o[4 * FS4 + ic], maskwall((lapT * kTco) * rinv - advT, lo, hi));

        // drou here so rxm/rxp die at end of this phase (uxm/uxp reloaded in phase 2 → L1 hits)
        const float4 uxm = s[0 * FS4 + ixm], uxp = s[0 * FS4 + ixp];
        __stcs(&o[3 * FS4 + ic], (rxm * uxm - rxp * uxp) * inv2dx);
    }

    // ---- phase 2: u ----
    {
        const float4 uxm = s[0 * FS4 + ixm], uxp = s[0 * FS4 + ixp];
        const float4 uym = s[0 * FS4 + iym], uyp = s[0 * FS4 + iyp];
        const float4 uzm = zm_of(uc), uzp = zp_of(uc);
        const float4 lapU = (uxp + uxm - uc * 2.0f) * invdx2 + (uyp + uym - uc * 2.0f) * invdy2 + (uzp + uzm - uc * 2.0f) * invdz2;
        const float4 advU = uc * ((uxp - uxm) * inv2dx) + vc * ((uyp - uym) * inv2dy) + wc * ((uzp - uzm) * inv2dz);
        __stcs(&o[0 * FS4 + ic], maskwall((lapU * MUc - dpdx) * rinv - advU, lo, hi));
    }

    // ---- phase 3: v ----
    {
        const float4 vxm = s[1 * FS4 + ixm], vxp = s[1 * FS4 + ixp];
        const float4 vym = s[1 * FS4 + iym], vyp = s[1 * FS4 + iyp];
        const float4 vzm = zm_of(vc), vzp = zp_of(vc);
        const float4 lapV = (vxp + vxm - vc * 2.0f) * invdx2 + (vyp + vym - vc * 2.0f) * invdy2 + (vzp + vzm - vc * 2.0f) * invdz2;
        const float4 advV = uc * ((vxp - vxm) * inv2dx) + vc * ((vyp - vym) * inv2dy) + wc * ((vzp - vzm) * inv2dz);
        __stcs(&o[1 * FS4 + ic], maskwall((lapV * MUc - dpdy) * rinv - advV, lo, hi));
    }

    // ---- phase 4: w  ((-G*rho)/rho == -G) ----
    {
        const float4 wxm = s[2 * FS4 + ixm], wxp = s[2 * FS4 + ixp];
        const float4 wym = s[2 * FS4 + iym], wyp = s[2 * FS4 + iyp];
        const float4 wzm = zm_of(wc), wzp = zp_of(wc);
        const float4 lapW = (wxp + wxm - wc * 2.0f) * invdx2 + (wyp + wym - wc * 2.0f) * invdy2 + (wzp + wzm - wc * 2.0f) * invdz2;
        const float4 advW = uc * ((wxp - wxm) * inv2dx) + vc * ((wyp - wym) * inv2dy) + wc * ((wzp - wzm) * inv2dz);
        float4 dw = (lapW * MUc - dpdz) * rinv - advW;
        dw = make_float4(dw.x - Gc, dw.y - Gc, dw.z - Gc, dw.w - Gc);
        __stcs(&o[2 * FS4 + ic], maskwall(dw, lo, hi));
    }

    // ---- phase 5: c (one-sided z at walls, NOT masked) ----
    {
        const float4 cc  = s[5 * FS4 + ic];
        const float4 cxm = s[5 * FS4 + ixm], cxp = s[5 * FS4 + ixp];
        const float4 cym = s[5 * FS4 + iym], cyp = s[5 * FS4 + iyp];
        const float4 czm = zm_of(cc), czp = zp_of(cc);

        float4 dcdz = (czp - czm) * inv2dz;
        if (lo) dcdz.x = (-3.0f * cc.x + 4.0f * cc.y - cc.z) * inv2dz;
        if (hi) dcdz.w = ( 3.0f * cc.w - 4.0f * cc.z + cc.y) * inv2dz;

        const float4 advC = uc * ((cxp - cxm) * inv2dx) + vc * ((cyp - cym) * inv2dy) + wc * dcdz;
        __stcs(&o[5 * FS4 + ic], make_float4(-advC.x, -advC.y, -advC.z, -advC.w));
    }
}
} // namespace

extern "C" void kernel_launch(void* const* d_in, const int* in_sizes, int n_in,
                              void* d_out, int out_size)
{
    const float4* s = (const float4*)d_in[0];
    float4* o = (float4*)d_out;
    dim3 block(32, 8, 1);             // 256 threads: 32 z-chunks × 8 y
    dim3 grid(NY / 8, NX, 1);         // 32 × 256 blocks
    rb4_kernel<<<grid, block>>>(s, o);
}